// round 6
// baseline (speedup 1.0000x reference)
#include <cuda_runtime.h>
#include <cstdint>

#define BATCH 8192
#define NH 4
#define DIM 2048
#define NDIM 8192
#define DFF 8192
#define EPSV 1.1920928955078125e-07f

// -------- scratch (static __device__, no allocations) --------
__device__ float g_dots[(size_t)BATCH * 32];      // cols 0-3 pre, 4-7 post, 8-23 res, 24 ss
__device__ float g_Hpre[(size_t)BATCH * 4];
__device__ float g_Hpost[(size_t)BATCH * 4];
__device__ float g_Hres[(size_t)BATCH * 16];
__device__ float g_xpre[(size_t)BATCH * DIM];     // 64 MB
__device__ float g_G[(size_t)BATCH * DFF];        // 256 MB gelu activations

// -------- helpers --------
__device__ __forceinline__ float to_tf32(float a) {
    unsigned u;
    asm("cvt.rna.tf32.f32 %0, %1;" : "=r"(u) : "f"(a));
    return __uint_as_float(u);
}

__device__ __forceinline__ void mma8(float* c, const unsigned* a, const unsigned* b) {
    asm volatile(
        "mma.sync.aligned.m16n8k8.row.col.f32.tf32.tf32.f32 "
        "{%0,%1,%2,%3}, {%4,%5,%6,%7}, {%8,%9}, {%0,%1,%2,%3};"
        : "+f"(c[0]), "+f"(c[1]), "+f"(c[2]), "+f"(c[3])
        : "r"(a[0]), "r"(a[1]), "r"(a[2]), "r"(a[3]), "r"(b[0]), "r"(b[1]));
}

__device__ __forceinline__ float gelu_exact(float v) {
    return 0.5f * v * (1.0f + erff(v * 0.70710678118654752440f));
}

// ============================================================
// K1: per-row dot products against theta columns (+ sum of squares)
// X[B, 8192] @ Theta[8192, 24], plus ss = sum(x^2). Theta (800KB) lives in L2.
// ============================================================
#define K1_TB 32
#define K1_KC 64

__global__ __launch_bounds__(256) void k1_dots(
    const float* __restrict__ x, const float* __restrict__ w,
    const float* __restrict__ tpre, const float* __restrict__ tpost,
    const float* __restrict__ tres) {
    __shared__ float xs[K1_TB][K1_KC + 1];
    __shared__ float ths[K1_KC][25];
    const int tid = threadIdx.x;
    const int col = tid & 31;   // 0..23 theta cols, 24+ ss
    const int rg  = tid >> 5;   // warp id = row group 0..7
    const int b0 = blockIdx.x * K1_TB;
    float acc[4] = {0.f, 0.f, 0.f, 0.f};

    for (int k0 = 0; k0 < NDIM; k0 += K1_KC) {
        for (int idx = tid; idx < K1_TB * K1_KC; idx += 256) {
            int r = idx >> 6, kk = idx & 63;
            xs[r][kk] = x[(size_t)(b0 + r) * NDIM + k0 + kk];
        }
        for (int idx = tid; idx < K1_KC * 24; idx += 256) {
            int kk = idx / 24, c = idx - kk * 24;
            int k = k0 + kk;
            float v;
            if (c < 4)       v = __ldg(&tpre[k * 4 + c]);
            else if (c < 8)  v = __ldg(&tpost[k * 4 + c - 4]);
            else             v = __ldg(&tres[k * 16 + c - 8]);
            ths[kk][c] = v * __ldg(&w[k]);   // fold rms_weight into theta
        }
        __syncthreads();
        if (col < 24) {
#pragma unroll 4
            for (int kk = 0; kk < K1_KC; kk++) {
                float tv = ths[kk][col];
#pragma unroll
                for (int i = 0; i < 4; i++) acc[i] += xs[rg + i * 8][kk] * tv;
            }
        } else {
#pragma unroll 4
            for (int kk = 0; kk < K1_KC; kk++) {
#pragma unroll
                for (int i = 0; i < 4; i++) {
                    float xv = xs[rg + i * 8][kk];
                    acc[i] += xv * xv;
                }
            }
        }
        __syncthreads();
    }
    if (col <= 24) {
#pragma unroll
        for (int i = 0; i < 4; i++)
            g_dots[(size_t)(b0 + rg + i * 8) * 32 + col] = acc[i];
    }
}

// ============================================================
// K2: heads — sigmoid gates + 4x4 sinkhorn (20 iters), one thread per batch row
// ============================================================
__global__ __launch_bounds__(256) void k2_heads(
    const float* __restrict__ apre, const float* __restrict__ apost,
    const float* __restrict__ ares, const float* __restrict__ bpre,
    const float* __restrict__ bpost, const float* __restrict__ bres) {
    int b = blockIdx.x * blockDim.x + threadIdx.x;
    if (b >= BATCH) return;
    const float* dr = &g_dots[(size_t)b * 32];
    float inv = rsqrtf(dr[24] / (float)NDIM + EPSV);
    float aP = *apre, aQ = *apost, aR = *ares;
#pragma unroll
    for (int h = 0; h < 4; h++) {
        float t = aP * dr[h] * inv + bpre[h];
        g_Hpre[(size_t)b * 4 + h] = 1.f / (1.f + expf(-t));
        t = aQ * dr[4 + h] * inv + bpost[h];
        g_Hpost[(size_t)b * 4 + h] = 2.f / (1.f + expf(-t));
    }
    float m[16];
#pragma unroll
    for (int j = 0; j < 16; j++) m[j] = expf(aR * dr[8 + j] * inv + bres[j]);
#pragma unroll 1
    for (int it = 0; it < 20; it++) {
#pragma unroll
        for (int r = 0; r < 4; r++) {
            float s = m[r * 4] + m[r * 4 + 1] + m[r * 4 + 2] + m[r * 4 + 3];
            float is = 1.f / s;
            m[r * 4] *= is; m[r * 4 + 1] *= is; m[r * 4 + 2] *= is; m[r * 4 + 3] *= is;
        }
#pragma unroll
        for (int c = 0; c < 4; c++) {
            float s = m[c] + m[c + 4] + m[c + 8] + m[c + 12];
            float is = 1.f / s;
            m[c] *= is; m[c + 4] *= is; m[c + 8] *= is; m[c + 12] *= is;
        }
    }
#pragma unroll
    for (int j = 0; j < 16; j++) g_Hres[(size_t)b * 16 + j] = m[j];
}

// ============================================================
// K3: x_pre = H_pre . x  and  h_l = H_res @ x  (h_l written to d_out)
// ============================================================
__global__ __launch_bounds__(256) void k3_mix(const float* __restrict__ x,
                                              float* __restrict__ out) {
    __shared__ float hp[4];
    __shared__ float hr[16];
    int b = blockIdx.y;
    int d = (blockIdx.x << 8) + threadIdx.x;
    if (threadIdx.x < 4)  hp[threadIdx.x] = g_Hpre[(size_t)b * 4 + threadIdx.x];
    if (threadIdx.x < 16) hr[threadIdx.x] = g_Hres[(size_t)b * 16 + threadIdx.x];
    __syncthreads();
    size_t xb = (size_t)b * NH * DIM + d;
    float x0 = x[xb], x1 = x[xb + DIM], x2 = x[xb + 2 * DIM], x3 = x[xb + 3 * DIM];
    g_xpre[(size_t)b * DIM + d] = hp[0] * x0 + hp[1] * x1 + hp[2] * x2 + hp[3] * x3;
#pragma unroll
    for (int n = 0; n < 4; n++)
        out[xb + (size_t)n * DIM] =
            hr[n * 4] * x0 + hr[n * 4 + 1] * x1 + hr[n * 4 + 2] * x2 + hr[n * 4 + 3] * x3;
}

// ============================================================
// K4: G = gelu(x_pre @ W1 + b1)   [8192 x 2048] @ [2048 x 8192]
// tf32 mma.sync, 128x128x16 block tile, 8 warps of 64x32, reg-prefetch pipeline
// ============================================================
__global__ __launch_bounds__(256, 2) void k4_gemm1(const float* __restrict__ W1,
                                                   const float* __restrict__ bias1) {
    __shared__ float As[128][20];
    __shared__ float Bs[16][132];
    const int tid = threadIdx.x;
    const int lane = tid & 31, wid = tid >> 5;
    const int wm = (wid & 1) << 6;
    const int wn = (wid >> 1) << 5;
    const int m0 = blockIdx.y << 7;
    const int n0 = blockIdx.x << 7;
    const int tig = lane & 3, grp = lane >> 2;
    const int ar = tid >> 2, ac = (tid & 3) << 2;
    const int br = tid >> 5, bc = (tid & 31) << 2;
    float acc[4][4][4];
#pragma unroll
    for (int i = 0; i < 4; i++)
#pragma unroll
        for (int j = 0; j < 4; j++)
#pragma unroll
            for (int q = 0; q < 4; q++) acc[i][j][q] = 0.f;

    float4 av0 = *(const float4*)&g_xpre[(size_t)(m0 + ar) * DIM + ac];
    float4 av1 = *(const float4*)&g_xpre[(size_t)(m0 + ar + 64) * DIM + ac];
    float4 bv0 = *(const float4*)&W1[(size_t)br * DFF + n0 + bc];
    float4 bv1 = *(const float4*)&W1[(size_t)(br + 8) * DFF + n0 + bc];

#pragma unroll 1
    for (int k0 = 0; k0 < DIM; k0 += 16) {
        __syncthreads();
        *(float4*)&As[ar][ac] =
            make_float4(to_tf32(av0.x), to_tf32(av0.y), to_tf32(av0.z), to_tf32(av0.w));
        *(float4*)&As[ar + 64][ac] =
            make_float4(to_tf32(av1.x), to_tf32(av1.y), to_tf32(av1.z), to_tf32(av1.w));
        *(float4*)&Bs[br][bc] =
            make_float4(to_tf32(bv0.x), to_tf32(bv0.y), to_tf32(bv0.z), to_tf32(bv0.w));
        *(float4*)&Bs[br + 8][bc] =
            make_float4(to_tf32(bv1.x), to_tf32(bv1.y), to_tf32(bv1.z), to_tf32(bv1.w));
        __syncthreads();
        int kn = k0 + 16;
        if (kn < DIM) {
            av0 = *(const float4*)&g_xpre[(size_t)(m0 + ar) * DIM + kn + ac];
            av1 = *(const float4*)&g_xpre[(size_t)(m0 + ar + 64) * DIM + kn + ac];
            bv0 = *(const float4*)&W1[(size_t)(kn + br) * DFF + n0 + bc];
            bv1 = *(const float4*)&W1[(size_t)(kn + br + 8) * DFF + n0 + bc];
        }
#pragma unroll
        for (int ks = 0; ks < 2; ks++) {
            const int kb = ks << 3;
            unsigned af[4][4], bf[4][2];
#pragma unroll
            for (int mt = 0; mt < 4; mt++) {
                int r = wm + (mt << 4) + grp;
                af[mt][0] = __float_as_uint(As[r][kb + tig]);
                af[mt][1] = __float_as_uint(As[r + 8][kb + tig]);
                af[mt][2] = __float_as_uint(As[r][kb + tig + 4]);
                af[mt][3] = __float_as_uint(As[r + 8][kb + tig + 4]);
            }
#pragma unroll
            for (int nt = 0; nt < 4; nt++) {
                int c = wn + (nt << 3) + grp;
                bf[nt][0] = __float_as_uint(Bs[kb + tig][c]);
                bf[nt][1] = __float_as_uint(Bs[kb + tig + 4][c]);
            }
#pragma unroll
            for (int mt = 0; mt < 4; mt++)
#pragma unroll
                for (int nt = 0; nt < 4; nt++) mma8(acc[mt][nt], af[mt], bf[nt]);
        }
    }
#pragma unroll
    for (int mt = 0; mt < 4; mt++) {
        int r = m0 + wm + (mt << 4) + grp;
#pragma unroll
        for (int nt = 0; nt < 4; nt++) {
            int c = n0 + wn + (nt << 3) + (tig << 1);
            float bb0 = __ldg(&bias1[c]), bb1 = __ldg(&bias1[c + 1]);
            g_G[(size_t)r * DFF + c]         = gelu_exact(acc[mt][nt][0] + bb0);
            g_G[(size_t)r * DFF + c + 1]     = gelu_exact(acc[mt][nt][1] + bb1);
            g_G[(size_t)(r + 8) * DFF + c]     = gelu_exact(acc[mt][nt][2] + bb0);
            g_G[(size_t)(r + 8) * DFF + c + 1] = gelu_exact(acc[mt][nt][3] + bb1);
        }
    }
}

// ============================================================
// K5: H_bar = G @ W2 + b2 ; out = H_post[b,h]*H_bar[b,d] + out (h_l from K3)
// ============================================================
__global__ __launch_bounds__(256, 2) void k5_gemm2(const float* __restrict__ W2,
                                                   const float* __restrict__ bias2,
                                                   float* __restrict__ out) {
    __shared__ float As[128][20];
    __shared__ float Bs[16][132];
    __shared__ float hps[128][4];
    const int tid = threadIdx.x;
    const int lane = tid & 31, wid = tid >> 5;
    const int wm = (wid & 1) << 6;
    const int wn = (wid >> 1) << 5;
    const int m0 = blockIdx.y << 7;
    const int n0 = blockIdx.x << 7;
    const int tig = lane & 3, grp = lane >> 2;
    const int ar = tid >> 2, ac = (tid & 3) << 2;
    const int br = tid >> 5, bc = (tid & 31) << 2;

    for (int i = tid; i < 512; i += 256)
        hps[i >> 2][i & 3] = g_Hpost[(size_t)(m0 + (i >> 2)) * 4 + (i & 3)];

    float acc[4][4][4];
#pragma unroll
    for (int i = 0; i < 4; i++)
#pragma unroll
        for (int j = 0; j < 4; j++)
#pragma unroll
            for (int q = 0; q < 4; q++) acc[i][j][q] = 0.f;

    float4 av0 = *(const float4*)&g_G[(size_t)(m0 + ar) * DFF + ac];
    float4 av1 = *(const float4*)&g_G[(size_t)(m0 + ar + 64) * DFF + ac];
    float4 bv0 = *(const float4*)&W2[(size_t)br * DIM + n0 + bc];
    float4 bv1 = *(const float4*)&W2[(size_t)(br + 8) * DIM + n0 + bc];

#pragma unroll 1
    for (int k0 = 0; k0 < DFF; k0 += 16) {
        __syncthreads();
        *(float4*)&As[ar][ac] =
            make_float4(to_tf32(av0.x), to_tf32(av0.y), to_tf32(av0.z), to_tf32(av0.w));
        *(float4*)&As[ar + 64][ac] =
            make_float4(to_tf32(av1.x), to_tf32(av1.y), to_tf32(av1.z), to_tf32(av1.w));
        *(float4*)&Bs[br][bc] =
            make_float4(to_tf32(bv0.x), to_tf32(bv0.y), to_tf32(bv0.z), to_tf32(bv0.w));
        *(float4*)&Bs[br + 8][bc] =
            make_float4(to_tf32(bv1.x), to_tf32(bv1.y), to_tf32(bv1.z), to_tf32(bv1.w));
        __syncthreads();
        int kn = k0 + 16;
        if (kn < DFF) {
            av0 = *(const float4*)&g_G[(size_t)(m0 + ar) * DFF + kn + ac];
            av1 = *(const float4*)&g_G[(size_t)(m0 + ar + 64) * DFF + kn + ac];
            bv0 = *(const float4*)&W2[(size_t)(kn + br) * DIM + n0 + bc];
            bv1 = *(const float4*)&W2[(size_t)(kn + br + 8) * DIM + n0 + bc];
        }
#pragma unroll
        for (int ks = 0; ks < 2; ks++) {
            const int kb = ks << 3;
            unsigned af[4][4], bf[4][2];
#pragma unroll
            for (int mt = 0; mt < 4; mt++) {
                int r = wm + (mt << 4) + grp;
                af[mt][0] = __float_as_uint(As[r][kb + tig]);
                af[mt][1] = __float_as_uint(As[r + 8][kb + tig]);
                af[mt][2] = __float_as_uint(As[r][kb + tig + 4]);
                af[mt][3] = __float_as_uint(As[r + 8][kb + tig + 4]);
            }
#pragma unroll
            for (int nt = 0; nt < 4; nt++) {
                int c = wn + (nt << 3) + grp;
                bf[nt][0] = __float_as_uint(Bs[kb + tig][c]);
                bf[nt][1] = __float_as_uint(Bs[kb + tig + 4][c]);
            }
#pragma unroll
            for (int mt = 0; mt < 4; mt++)
#pragma unroll
                for (int nt = 0; nt < 4; nt++) mma8(acc[mt][nt], af[mt], bf[nt]);
        }
    }
    // epilogue: out[b, h, d] = H_post[b,h] * (acc + b2[d]) + h_l (already in out)
#pragma unroll
    for (int mt = 0; mt < 4; mt++) {
        int rl = wm + (mt << 4) + grp;
#pragma unroll
        for (int nt = 0; nt < 4; nt++) {
            int cc = n0 + wn + (nt << 3) + (tig << 1);
            float b20 = __ldg(&bias2[cc]), b21 = __ldg(&bias2[cc + 1]);
#pragma unroll
            for (int half = 0; half < 2; half++) {
                int r = rl + half * 8;
                float h0 = acc[mt][nt][half * 2 + 0] + b20;
                float h1 = acc[mt][nt][half * 2 + 1] + b21;
                size_t base = ((size_t)(m0 + r) * 4) * DIM + cc;
#pragma unroll
                for (int h = 0; h < 4; h++) {
                    float hp = hps[r][h];
                    size_t o = base + (size_t)h * DIM;
                    out[o]     = fmaf(hp, h0, out[o]);
                    out[o + 1] = fmaf(hp, h1, out[o + 1]);
                }
            }
        }
    }
}

// ============================================================
extern "C" void kernel_launch(void* const* d_in, const int* in_sizes, int n_in,
                              void* d_out, int out_size) {
    const float* x     = (const float*)d_in[0];
    const float* w     = (const float*)d_in[1];
    const float* tpre  = (const float*)d_in[2];
    const float* tpost = (const float*)d_in[3];
    const float* tres  = (const float*)d_in[4];
    const float* apre  = (const float*)d_in[5];
    const float* apost = (const float*)d_in[6];
    const float* ares  = (const float*)d_in[7];
    const float* bpre  = (const float*)d_in[8];
    const float* bpost = (const float*)d_in[9];
    const float* bres  = (const float*)d_in[10];
    const float* W1    = (const float*)d_in[11];
    const float* b1    = (const float*)d_in[12];
    const float* W2    = (const float*)d_in[13];
    const float* b2    = (const float*)d_in[14];
    float* out = (float*)d_out;

    k1_dots<<<BATCH / K1_TB, 256>>>(x, w, tpre, tpost, tres);
    k2_heads<<<BATCH / 256, 256>>>(apre, apost, ares, bpre, bpost, bres);
    k3_mix<<<dim3(DIM / 256, BATCH), 256>>>(x, out);
    k4_gemm1<<<dim3(DFF / 128, BATCH / 128), 256>>>(W1, b1);
    k5_gemm2<<<dim3(DIM / 128, BATCH / 128), 256>>>(W2, b2, out);
}

// round 9
// speedup vs baseline: 1.0525x; 1.0525x over previous
#include <cuda_runtime.h>
#include <cstdint>

#define BATCH 8192
#define NH 4
#define DIM 2048
#define NDIM 8192
#define DFF 8192
#define EPSV 1.1920928955078125e-07f

typedef unsigned long long ull;

// -------- scratch (static __device__, no allocations) --------
__device__ float g_dots[(size_t)BATCH * 32];
__device__ float g_Hpre[(size_t)BATCH * 4];
__device__ float g_Hpost[(size_t)BATCH * 4];
__device__ float g_Hres[(size_t)BATCH * 16];
__device__ float g_xpre[(size_t)BATCH * DIM];        // tf32-rounded
__device__ float g_G[(size_t)BATCH * DFF];           // tf32-rounded gelu acts
__device__ float g_W1t[(size_t)DIM * DFF];           // tf32-rounded W1
__device__ float g_W2t[(size_t)DFF * DIM];           // tf32-rounded W2

// -------- helpers --------
__device__ __forceinline__ float to_tf32(float a) {
    unsigned u;
    asm("cvt.rna.tf32.f32 %0, %1;" : "=r"(u) : "f"(a));
    return __uint_as_float(u);
}
__device__ __forceinline__ void mma8(float* c, const unsigned* a, const unsigned* b) {
    asm volatile(
        "mma.sync.aligned.m16n8k8.row.col.f32.tf32.tf32.f32 "
        "{%0,%1,%2,%3}, {%4,%5,%6,%7}, {%8,%9}, {%0,%1,%2,%3};"
        : "+f"(c[0]), "+f"(c[1]), "+f"(c[2]), "+f"(c[3])
        : "r"(a[0]), "r"(a[1]), "r"(a[2]), "r"(a[3]), "r"(b[0]), "r"(b[1]));
}
__device__ __forceinline__ float gelu_exact(float v) {
    return 0.5f * v * (1.0f + erff(v * 0.70710678118654752440f));
}
__device__ __forceinline__ uint32_t smem_u32(const void* p) {
    uint32_t a;
    asm("{ .reg .u64 t; cvta.to.shared.u64 t, %1; cvt.u32.u64 %0, t; }" : "=r"(a) : "l"(p));
    return a;
}
__device__ __forceinline__ void cpa16(uint32_t dst, const float* src) {
    asm volatile("cp.async.cg.shared.global [%0], [%1], 16;" :: "r"(dst), "l"(src));
}
__device__ __forceinline__ void ldsm4(unsigned* r, uint32_t addr) {
    asm volatile("ldmatrix.sync.aligned.m8n8.x4.shared.b16 {%0,%1,%2,%3}, [%4];"
                 : "=r"(r[0]), "=r"(r[1]), "=r"(r[2]), "=r"(r[3]) : "r"(addr));
}
__device__ __forceinline__ ull pk2(float lo, float hi) {
    ull r; asm("mov.b64 %0, {%1,%2};" : "=l"(r) : "f"(lo), "f"(hi)); return r;
}
__device__ __forceinline__ void upk2(ull v, float& lo, float& hi) {
    asm("mov.b64 {%0,%1}, %2;" : "=f"(lo), "=f"(hi) : "l"(v));
}
__device__ __forceinline__ ull fma2(ull a, ull b, ull c) {
    ull d; asm("fma.rn.f32x2 %0, %1, %2, %3;" : "=l"(d) : "l"(a), "l"(b), "l"(c)); return d;
}

// ============================================================
// K0: pre-round W1, W2 to tf32 scratch copies
// ============================================================
#define W1_F4 ((DIM * DFF) / 4)
#define W2_F4 ((DFF * DIM) / 4)
__global__ __launch_bounds__(256) void k0_cvt(const float* __restrict__ W1,
                                              const float* __restrict__ W2) {
    size_t i = (size_t)blockIdx.x * 256 + threadIdx.x;
    if (i < W1_F4) {
        float4 v = ((const float4*)W1)[i];
        v.x = to_tf32(v.x); v.y = to_tf32(v.y); v.z = to_tf32(v.z); v.w = to_tf32(v.w);
        ((float4*)g_W1t)[i] = v;
    } else {
        size_t j = i - W1_F4;
        if (j < W2_F4) {
            float4 v = ((const float4*)W2)[j];
            v.x = to_tf32(v.x); v.y = to_tf32(v.y); v.z = to_tf32(v.z); v.w = to_tf32(v.w);
            ((float4*)g_W2t)[j] = v;
        }
    }
}

// ============================================================
// K1: X[B,8192] @ Theta[8192,24] + sum(x^2), f32x2-packed FMAs
// rows packed as pairs (p, p+16) within a 32-row block tile
// ============================================================
__global__ __launch_bounds__(256) void k1_dots(
    const float* __restrict__ x, const float* __restrict__ w,
    const float* __restrict__ tpre, const float* __restrict__ tpost,
    const float* __restrict__ tres) {
    __shared__ float2 xs2[64][17];
    __shared__ float ths[64][25];
    const int tid = threadIdx.x;
    const int col = tid & 31;   // 0..23 theta cols, 24 = ss
    const int rg  = tid >> 5;   // warp id -> pair index
    const int b0 = blockIdx.x * 32;
    ull acc0 = pk2(0.f, 0.f), acc1 = pk2(0.f, 0.f);

    for (int k0 = 0; k0 < NDIM; k0 += 64) {
        // stage x rows as (p, p+16) pairs, coalesced along kk
#pragma unroll
        for (int j = 0; j < 4; j++) {
            int idx = tid + j * 256;
            int p = idx >> 6, kk = idx & 63;
            float lo = x[(size_t)(b0 + p) * NDIM + k0 + kk];
            float hi = x[(size_t)(b0 + p + 16) * NDIM + k0 + kk];
            xs2[kk][p] = make_float2(lo, hi);
        }
        // stage theta * rms_weight
        for (int idx = tid; idx < 64 * 24; idx += 256) {
            int kk = idx / 24, c = idx - kk * 24;
            int k = k0 + kk;
            float v;
            if (c < 4)       v = __ldg(&tpre[k * 4 + c]);
            else if (c < 8)  v = __ldg(&tpost[k * 4 + c - 4]);
            else             v = __ldg(&tres[k * 16 + c - 8]);
            ths[kk][c] = v * __ldg(&w[k]);
        }
        __syncthreads();
        if (col < 24) {
#pragma unroll 8
            for (int kk = 0; kk < 64; kk++) {
                float tv = ths[kk][col];
                ull t2 = pk2(tv, tv);
                acc0 = fma2(*(const ull*)&xs2[kk][rg], t2, acc0);
                acc1 = fma2(*(const ull*)&xs2[kk][rg + 8], t2, acc1);
            }
        } else if (col == 24) {
#pragma unroll 8
            for (int kk = 0; kk < 64; kk++) {
                ull v0 = *(const ull*)&xs2[kk][rg];
                ull v1 = *(const ull*)&xs2[kk][rg + 8];
                acc0 = fma2(v0, v0, acc0);
                acc1 = fma2(v1, v1, acc1);
            }
        }
        __syncthreads();
    }
    if (col <= 24) {
        float l0, h0, l1, h1;
        upk2(acc0, l0, h0); upk2(acc1, l1, h1);
        g_dots[(size_t)(b0 + rg) * 32 + col]      = l0;
        g_dots[(size_t)(b0 + rg + 16) * 32 + col] = h0;
        g_dots[(size_t)(b0 + rg + 8) * 32 + col]  = l1;
        g_dots[(size_t)(b0 + rg + 24) * 32 + col] = h1;
    }
}

// ============================================================
// K2: sigmoid gates + 4x4 sinkhorn (20 iters)
// ============================================================
__global__ __launch_bounds__(256) void k2_heads(
    const float* __restrict__ apre, const float* __restrict__ apost,
    const float* __restrict__ ares, const float* __restrict__ bpre,
    const float* __restrict__ bpost, const float* __restrict__ bres) {
    int b = blockIdx.x * blockDim.x + threadIdx.x;
    if (b >= BATCH) return;
    const float* dr = &g_dots[(size_t)b * 32];
    float inv = rsqrtf(dr[24] / (float)NDIM + EPSV);
    float aP = *apre, aQ = *apost, aR = *ares;
#pragma unroll
    for (int h = 0; h < 4; h++) {
        float t = aP * dr[h] * inv + bpre[h];
        g_Hpre[(size_t)b * 4 + h] = 1.f / (1.f + expf(-t));
        t = aQ * dr[4 + h] * inv + bpost[h];
        g_Hpost[(size_t)b * 4 + h] = 2.f / (1.f + expf(-t));
    }
    float m[16];
#pragma unroll
    for (int j = 0; j < 16; j++) m[j] = expf(aR * dr[8 + j] * inv + bres[j]);
#pragma unroll 1
    for (int it = 0; it < 20; it++) {
#pragma unroll
        for (int r = 0; r < 4; r++) {
            float s = m[r * 4] + m[r * 4 + 1] + m[r * 4 + 2] + m[r * 4 + 3];
            float is = 1.f / s;
            m[r * 4] *= is; m[r * 4 + 1] *= is; m[r * 4 + 2] *= is; m[r * 4 + 3] *= is;
        }
#pragma unroll
        for (int c = 0; c < 4; c++) {
            float s = m[c] + m[c + 4] + m[c + 8] + m[c + 12];
            float is = 1.f / s;
            m[c] *= is; m[c + 4] *= is; m[c + 8] *= is; m[c + 12] *= is;
        }
    }
#pragma unroll
    for (int j = 0; j < 16; j++) g_Hres[(size_t)b * 16 + j] = m[j];
}

// ============================================================
// K3: x_pre (tf32-rounded) and h_l -> d_out
// ============================================================
__global__ __launch_bounds__(256) void k3_mix(const float* __restrict__ x,
                                              float* __restrict__ out) {
    __shared__ float hp[4];
    __shared__ float hr[16];
    int b = blockIdx.y;
    int d = (blockIdx.x << 8) + threadIdx.x;
    if (threadIdx.x < 4)  hp[threadIdx.x] = g_Hpre[(size_t)b * 4 + threadIdx.x];
    if (threadIdx.x < 16) hr[threadIdx.x] = g_Hres[(size_t)b * 16 + threadIdx.x];
    __syncthreads();
    size_t xb = (size_t)b * NH * DIM + d;
    float x0 = x[xb], x1 = x[xb + DIM], x2 = x[xb + 2 * DIM], x3 = x[xb + 3 * DIM];
    g_xpre[(size_t)b * DIM + d] =
        to_tf32(hp[0] * x0 + hp[1] * x1 + hp[2] * x2 + hp[3] * x3);
#pragma unroll
    for (int n = 0; n < 4; n++)
        out[xb + (size_t)n * DIM] =
            hr[n * 4] * x0 + hr[n * 4 + 1] * x1 + hr[n * 4 + 2] * x2 + hr[n * 4 + 3] * x3;
}

// ============================================================
// GEMM common: 128x128 block, 8 warps (2m x 4n) of 64x32, 3-stage cp.async,
// ldmatrix.x4 A-fragments, scalar-LDS B-fragments.
// Stage layout (floats): As[128][20] (2560) then Bs[16][132] (2112) = 4672.
// ============================================================
#define STG_F 4672
#define STG_B (STG_F * 4)
#define AS_PAD 20
#define BS_PAD 132
#define NSTAGE 3
#define GEMM_SMEM (NSTAGE * STG_B)

struct GemmCtx {
    uint32_t sb;          // smem u32 base
    uint32_t a_d0, a_d1, b_d0, b_d1;   // cp.async dst byte offsets in stage
    uint32_t a_lm;        // ldmatrix base byte offset in stage (lane-resolved)
    int wm, wn, tig, grp;
};

__device__ __forceinline__ void gemm_init(GemmCtx& c, const float* smbase, int tid) {
    c.sb = smem_u32(smbase);
    int lane = tid & 31, wid = tid >> 5;
    c.wm = (wid & 1) << 6;
    c.wn = (wid >> 1) << 5;
    c.tig = lane & 3;
    c.grp = lane >> 2;
    c.a_d0 = ((tid >> 2) * AS_PAD + (tid & 3) * 4) * 4;
    c.a_d1 = c.a_d0 + 64 * AS_PAD * 4;
    c.b_d0 = 2560 * 4 + ((tid >> 5) * BS_PAD + (tid & 31) * 4) * 4;
    c.b_d1 = c.b_d0 + 8 * BS_PAD * 4;
    c.a_lm = ((c.wm + (lane & 15)) * AS_PAD + ((lane >> 4) << 2)) * 4;
}

__device__ __forceinline__ void gemm_load(const GemmCtx& c, int s,
                                          const float* ap, int a_ld,
                                          const float* bp, int b_ld) {
    uint32_t so = c.sb + s * STG_B;
    cpa16(so + c.a_d0, ap);
    cpa16(so + c.a_d1, ap + (size_t)64 * a_ld);
    cpa16(so + c.b_d0, bp);
    cpa16(so + c.b_d1, bp + (size_t)8 * b_ld);
}

__device__ __forceinline__ void gemm_compute(const GemmCtx& c, int s,
                                             const float* smbase, float acc[4][4][4]) {
    const float* Bst = smbase + s * STG_F + 2560;
    uint32_t abase = c.sb + s * STG_B + c.a_lm;
#pragma unroll
    for (int ks = 0; ks < 2; ks++) {
        const int kb = ks << 3;
        unsigned af[4][4], bf[4][2];
#pragma unroll
        for (int mt = 0; mt < 4; mt++)
            ldsm4(af[mt], abase + mt * (16 * AS_PAD * 4) + kb * 4);
        const float* br0 = Bst + (kb + c.tig) * BS_PAD + c.wn + c.grp;
        const float* br1 = br0 + 4 * BS_PAD;
#pragma unroll
        for (int nt = 0; nt < 4; nt++) {
            bf[nt][0] = __float_as_uint(br0[nt * 8]);
            bf[nt][1] = __float_as_uint(br1[nt * 8]);
        }
#pragma unroll
        for (int mt = 0; mt < 4; mt++)
#pragma unroll
            for (int nt = 0; nt < 4; nt++) mma8(acc[mt][nt], af[mt], bf[nt]);
    }
}

// ============================================================
// K4: G = tf32(gelu(x_pre @ W1t + b1))   [8192x2048]@[2048x8192]
// ============================================================
__global__ __launch_bounds__(256, 2) void k4_gemm1(const float* __restrict__ bias1) {
    extern __shared__ float sm[];
    const int tid = threadIdx.x;
    const int m0 = blockIdx.y << 7;
    const int n0 = blockIdx.x << 7;
    GemmCtx c;
    gemm_init(c, sm, tid);

    const float* aptr = g_xpre + (size_t)(m0 + (tid >> 2)) * DIM + (tid & 3) * 4;
    const float* bptr = g_W1t + (size_t)(tid >> 5) * DFF + n0 + (tid & 31) * 4;

    float acc[4][4][4];
#pragma unroll
    for (int i = 0; i < 4; i++)
#pragma unroll
        for (int j = 0; j < 4; j++)
#pragma unroll
            for (int q = 0; q < 4; q++) acc[i][j][q] = 0.f;

    const int T = DIM / 16;
#pragma unroll
    for (int s = 0; s < 2; s++) {
        gemm_load(c, s, aptr + s * 16, DIM, bptr + (size_t)s * 16 * DFF, DFF);
        asm volatile("cp.async.commit_group;");
    }
#pragma unroll 1
    for (int i = 0; i < T; i++) {
        asm volatile("cp.async.wait_group 1;");
        __syncthreads();
        int nx = i + 2;
        if (nx < T)
            gemm_load(c, nx % NSTAGE, aptr + nx * 16, DIM,
                      bptr + (size_t)nx * 16 * DFF, DFF);
        asm volatile("cp.async.commit_group;");
        gemm_compute(c, i % NSTAGE, sm, acc);
    }
    // epilogue: gelu + bias, tf32-round, store
#pragma unroll
    for (int mt = 0; mt < 4; mt++) {
        int r = m0 + c.wm + (mt << 4) + c.grp;
#pragma unroll
        for (int nt = 0; nt < 4; nt++) {
            int cc = n0 + c.wn + (nt << 3) + (c.tig << 1);
            float bb0 = __ldg(&bias1[cc]), bb1 = __ldg(&bias1[cc + 1]);
            g_G[(size_t)r * DFF + cc]           = to_tf32(gelu_exact(acc[mt][nt][0] + bb0));
            g_G[(size_t)r * DFF + cc + 1]       = to_tf32(gelu_exact(acc[mt][nt][1] + bb1));
            g_G[(size_t)(r + 8) * DFF + cc]     = to_tf32(gelu_exact(acc[mt][nt][2] + bb0));
            g_G[(size_t)(r + 8) * DFF + cc + 1] = to_tf32(gelu_exact(acc[mt][nt][3] + bb1));
        }
    }
}

// ============================================================
// K5: H_bar = G @ W2t + b2 ; out += H_post * H_bar
// ============================================================
__global__ __launch_bounds__(256, 2) void k5_gemm2(const float* __restrict__ bias2,
                                                   float* __restrict__ out) {
    extern __shared__ float sm[];
    __shared__ float hps[128][4];
    const int tid = threadIdx.x;
    const int m0 = blockIdx.y << 7;
    const int n0 = blockIdx.x << 7;
    GemmCtx c;
    gemm_init(c, sm, tid);

    for (int i = tid; i < 512; i += 256)
        hps[i >> 2][i & 3] = g_Hpost[(size_t)(m0 + (i >> 2)) * 4 + (i & 3)];

    const float* aptr = g_G + (size_t)(m0 + (tid >> 2)) * DFF + (tid & 3) * 4;
    const float* bptr = g_W2t + (size_t)(tid >> 5) * DIM + n0 + (tid & 31) * 4;

    float acc[4][4][4];
#pragma unroll
    for (int i = 0; i < 4; i++)
#pragma unroll
        for (int j = 0; j < 4; j++)
#pragma unroll
            for (int q = 0; q < 4; q++) acc[i][j][q] = 0.f;

    const int T = DFF / 16;
#pragma unroll
    for (int s = 0; s < 2; s++) {
        gemm_load(c, s, aptr + s * 16, DFF, bptr + (size_t)s * 16 * DIM, DIM);
        asm volatile("cp.async.commit_group;");
    }
#pragma unroll 1
    for (int i = 0; i < T; i++) {
        asm volatile("cp.async.wait_group 1;");
        __syncthreads();
        int nx = i + 2;
        if (nx < T)
            gemm_load(c, nx % NSTAGE, aptr + nx * 16, DFF,
                      bptr + (size_t)nx * 16 * DIM, DIM);
        asm volatile("cp.async.commit_group;");
        gemm_compute(c, i % NSTAGE, sm, acc);
    }
    // epilogue: out[b,h,d] += H_post[b,h] * (acc + b2[d])
#pragma unroll
    for (int mt = 0; mt < 4; mt++) {
        int rl = c.wm + (mt << 4) + c.grp;
#pragma unroll
        for (int nt = 0; nt < 4; nt++) {
            int cc = n0 + c.wn + (nt << 3) + (c.tig << 1);
            float b20 = __ldg(&bias2[cc]), b21 = __ldg(&bias2[cc + 1]);
#pragma unroll
            for (int half = 0; half < 2; half++) {
                int r = rl + half * 8;
                float h0 = acc[mt][nt][half * 2 + 0] + b20;
                float h1 = acc[mt][nt][half * 2 + 1] + b21;
                size_t base = ((size_t)(m0 + r) * 4) * DIM + cc;
#pragma unroll
                for (int h = 0; h < 4; h++) {
                    float hp = hps[r][h];
                    size_t o = base + (size_t)h * DIM;
                    out[o]     = fmaf(hp, h0, out[o]);
                    out[o + 1] = fmaf(hp, h1, out[o + 1]);
                }
            }
        }
    }
}

// ============================================================
extern "C" void kernel_launch(void* const* d_in, const int* in_sizes, int n_in,
                              void* d_out, int out_size) {
    const float* x     = (const float*)d_in[0];
    const float* w     = (const float*)d_in[1];
    const float* tpre  = (const float*)d_in[2];
    const float* tpost = (const float*)d_in[3];
    const float* tres  = (const float*)d_in[4];
    const float* apre  = (const float*)d_in[5];
    const float* apost = (const float*)d_in[6];
    const float* ares  = (const float*)d_in[7];
    const float* bpre  = (const float*)d_in[8];
    const float* bpost = (const float*)d_in[9];
    const float* bres  = (const float*)d_in[10];
    const float* b1    = (const float*)d_in[12];
    const float* b2    = (const float*)d_in[14];
    float* out = (float*)d_out;

    cudaFuncSetAttribute(k4_gemm1, cudaFuncAttributeMaxDynamicSharedMemorySize, GEMM_SMEM);
    cudaFuncSetAttribute(k5_gemm2, cudaFuncAttributeMaxDynamicSharedMemorySize, GEMM_SMEM);

    k0_cvt<<<(W1_F4 + W2_F4 + 255) / 256, 256>>>((const float*)d_in[11],
                                                 (const float*)d_in[13]);
    k1_dots<<<BATCH / 32, 256>>>(x, w, tpre, tpost, tres);
    k2_heads<<<BATCH / 256, 256>>>(apre, apost, ares, bpre, bpost, bres);
    k3_mix<<<dim3(DIM / 256, BATCH), 256>>>(x, out);
    k4_gemm1<<<dim3(DFF / 128, BATCH / 128), 256, GEMM_SMEM>>>(b1);
    k5_gemm2<<<dim3(DIM / 128, BATCH / 128), 256, GEMM_SMEM>>>(b2, out);
}

// round 10
// speedup vs baseline: 1.2924x; 1.2279x over previous
#include <cuda_runtime.h>
#include <cstdint>

#define BATCH 8192
#define NH 4
#define DIM 2048
#define NDIM 8192
#define DFF 8192
#define EPSV 1.1920928955078125e-07f

typedef unsigned long long ull;

// -------- scratch (static __device__, no allocations) --------
__device__ float g_dots[(size_t)BATCH * 32];
__device__ float g_Hpre[(size_t)BATCH * 4];
__device__ float g_Hpost[(size_t)BATCH * 4];
__device__ float g_Hres[(size_t)BATCH * 16];
__device__ float g_xpre[(size_t)BATCH * DIM];        // tf32-rounded
__device__ float g_G[(size_t)BATCH * DFF];           // tf32-rounded gelu acts
__device__ float g_W1t[(size_t)DIM * DFF];           // tf32-rounded W1
__device__ float g_W2t[(size_t)DFF * DIM];           // tf32-rounded W2

// -------- helpers --------
__device__ __forceinline__ float to_tf32(float a) {
    unsigned u;
    asm("cvt.rna.tf32.f32 %0, %1;" : "=r"(u) : "f"(a));
    return __uint_as_float(u);
}
__device__ __forceinline__ void mma8(float* c, const unsigned* a, const unsigned* b) {
    asm volatile(
        "mma.sync.aligned.m16n8k8.row.col.f32.tf32.tf32.f32 "
        "{%0,%1,%2,%3}, {%4,%5,%6,%7}, {%8,%9}, {%0,%1,%2,%3};"
        : "+f"(c[0]), "+f"(c[1]), "+f"(c[2]), "+f"(c[3])
        : "r"(a[0]), "r"(a[1]), "r"(a[2]), "r"(a[3]), "r"(b[0]), "r"(b[1]));
}
__device__ __forceinline__ float gelu_exact(float v) {
    return 0.5f * v * (1.0f + erff(v * 0.70710678118654752440f));
}
__device__ __forceinline__ uint32_t smem_u32(const void* p) {
    uint32_t a;
    asm("{ .reg .u64 t; cvta.to.shared.u64 t, %1; cvt.u32.u64 %0, t; }" : "=r"(a) : "l"(p));
    return a;
}
__device__ __forceinline__ void cpa16(uint32_t dst, const float* src) {
    asm volatile("cp.async.cg.shared.global [%0], [%1], 16;" :: "r"(dst), "l"(src));
}
__device__ __forceinline__ void ldsm4(unsigned* r, uint32_t addr) {
    asm volatile("ldmatrix.sync.aligned.m8n8.x4.shared.b16 {%0,%1,%2,%3}, [%4];"
                 : "=r"(r[0]), "=r"(r[1]), "=r"(r[2]), "=r"(r[3]) : "r"(addr));
}

// ============================================================
// K0: pre-round W1, W2 to tf32 scratch copies
// ============================================================
#define W1_F4 ((DIM * DFF) / 4)
#define W2_F4 ((DFF * DIM) / 4)
__global__ __launch_bounds__(256) void k0_cvt(const float* __restrict__ W1,
                                              const float* __restrict__ W2) {
    size_t i = (size_t)blockIdx.x * 256 + threadIdx.x;
    if (i < W1_F4) {
        float4 v = ((const float4*)W1)[i];
        v.x = to_tf32(v.x); v.y = to_tf32(v.y); v.z = to_tf32(v.z); v.w = to_tf32(v.w);
        ((float4*)g_W1t)[i] = v;
    } else {
        size_t j = i - W1_F4;
        if (j < W2_F4) {
            float4 v = ((const float4*)W2)[j];
            v.x = to_tf32(v.x); v.y = to_tf32(v.y); v.z = to_tf32(v.z); v.w = to_tf32(v.w);
            ((float4*)g_W2t)[j] = v;
        }
    }
}

// ============================================================
// K1: tensor-core dots. X[32-row tile, 8192] @ Theta'[8192, 32(24 used)]
// 8 warps as 2m x 4n over 32x32 output; ss = sum(x^2) on same staged tiles.
// ============================================================
__global__ __launch_bounds__(256) void k1_dots(
    const float* __restrict__ x, const float* __restrict__ w,
    const float* __restrict__ tpre, const float* __restrict__ tpost,
    const float* __restrict__ tres) {
    __shared__ float xs[32][36];
    __shared__ float ths[32][40];
    const int tid = threadIdx.x;
    const int lane = tid & 31, wid = tid >> 5;
    const int wm = (wid & 1) << 4;          // 0 | 16
    const int wn = (wid >> 1) << 3;         // 0,8,16,24
    const int tig = lane & 3, grp = lane >> 2;
    const int b0 = blockIdx.x * 32;

    const uint32_t xsb = smem_u32(&xs[0][0]);
    const uint32_t a_lm = xsb + (((wm + (lane & 15)) * 36 + ((lane >> 4) << 2)) << 2);
    const uint32_t adst = xsb + ((((tid >> 3) * 36) + ((tid & 7) << 2)) << 2);
    const float* asrc = x + (size_t)(b0 + (tid >> 3)) * NDIM + ((tid & 7) << 2);
    const int srow = tid >> 3, scol = tid & 7;

    float acc[4] = {0.f, 0.f, 0.f, 0.f};
    float ss = 0.f;

#pragma unroll 1
    for (int k0 = 0; k0 < NDIM; k0 += 32) {
        cpa16(adst, asrc + k0);
        asm volatile("cp.async.commit_group;");
        // stage theta (cols 24..31 zero), rms_weight folded
#pragma unroll
        for (int j = 0; j < 4; j++) {
            int idx = tid + j * 256;
            int kk = idx >> 5, cc = idx & 31;
            int k = k0 + kk;
            float v = 0.f;
            if (cc < 4)       v = __ldg(&tpre[k * 4 + cc]);
            else if (cc < 8)  v = __ldg(&tpost[k * 4 + cc - 4]);
            else if (cc < 24) v = __ldg(&tres[k * 16 + cc - 8]);
            ths[kk][cc] = v * __ldg(&w[k]);
        }
        asm volatile("cp.async.wait_group 0;");
        __syncthreads();
#pragma unroll
        for (int ks = 0; ks < 4; ks++) {
            const int kb = ks << 3;
            unsigned af[4], bf[2];
            ldsm4(af, a_lm + kb * 4);
            bf[0] = __float_as_uint(ths[kb + tig][wn + grp]);
            bf[1] = __float_as_uint(ths[kb + tig + 4][wn + grp]);
            mma8(acc, af, bf);
        }
#pragma unroll
        for (int j = 0; j < 4; j++) {
            float xv = xs[srow][scol + 8 * j];
            ss = fmaf(xv, xv, ss);
        }
        __syncthreads();
    }
    // ss reduce across the 8 threads of each row (same warp, lane bits 0..2)
    ss += __shfl_xor_sync(0xFFFFFFFFu, ss, 4);
    ss += __shfl_xor_sync(0xFFFFFFFFu, ss, 2);
    ss += __shfl_xor_sync(0xFFFFFFFFu, ss, 1);
    if ((tid & 7) == 0) g_dots[(size_t)(b0 + srow) * 32 + 24] = ss;

    int r = b0 + wm + grp;
    int c = wn + (tig << 1);
    if (c < 24) {
        g_dots[(size_t)r * 32 + c]           = acc[0];
        g_dots[(size_t)r * 32 + c + 1]       = acc[1];
        g_dots[(size_t)(r + 8) * 32 + c]     = acc[2];
        g_dots[(size_t)(r + 8) * 32 + c + 1] = acc[3];
    }
}

// ============================================================
// K2: sigmoid gates + 4x4 sinkhorn (20 iters)
// ============================================================
__global__ __launch_bounds__(256) void k2_heads(
    const float* __restrict__ apre, const float* __restrict__ apost,
    const float* __restrict__ ares, const float* __restrict__ bpre,
    const float* __restrict__ bpost, const float* __restrict__ bres) {
    int b = blockIdx.x * blockDim.x + threadIdx.x;
    if (b >= BATCH) return;
    const float* dr = &g_dots[(size_t)b * 32];
    float inv = rsqrtf(dr[24] / (float)NDIM + EPSV);
    float aP = *apre, aQ = *apost, aR = *ares;
#pragma unroll
    for (int h = 0; h < 4; h++) {
        float t = aP * dr[h] * inv + bpre[h];
        g_Hpre[(size_t)b * 4 + h] = 1.f / (1.f + expf(-t));
        t = aQ * dr[4 + h] * inv + bpost[h];
        g_Hpost[(size_t)b * 4 + h] = 2.f / (1.f + expf(-t));
    }
    float m[16];
#pragma unroll
    for (int j = 0; j < 16; j++) m[j] = expf(aR * dr[8 + j] * inv + bres[j]);
#pragma unroll 1
    for (int it = 0; it < 20; it++) {
#pragma unroll
        for (int r = 0; r < 4; r++) {
            float s = m[r * 4] + m[r * 4 + 1] + m[r * 4 + 2] + m[r * 4 + 3];
            float is = 1.f / s;
            m[r * 4] *= is; m[r * 4 + 1] *= is; m[r * 4 + 2] *= is; m[r * 4 + 3] *= is;
        }
#pragma unroll
        for (int c = 0; c < 4; c++) {
            float s = m[c] + m[c + 4] + m[c + 8] + m[c + 12];
            float is = 1.f / s;
            m[c] *= is; m[c + 4] *= is; m[c + 8] *= is; m[c + 12] *= is;
        }
    }
#pragma unroll
    for (int j = 0; j < 16; j++) g_Hres[(size_t)b * 16 + j] = m[j];
}

// ============================================================
// K3: x_pre (tf32-rounded) and h_l -> d_out, float2 vectorized
// ============================================================
__global__ __launch_bounds__(256) void k3_mix(const float* __restrict__ x,
                                              float* __restrict__ out) {
    __shared__ float hp[4];
    __shared__ float hr[16];
    int b = blockIdx.y;
    int d2 = (blockIdx.x << 8) + threadIdx.x;   // float2 index within row (0..1023)
    if (threadIdx.x < 4)  hp[threadIdx.x] = g_Hpre[(size_t)b * 4 + threadIdx.x];
    if (threadIdx.x < 16) hr[threadIdx.x] = g_Hres[(size_t)b * 16 + threadIdx.x];
    __syncthreads();
    const float2* x2 = (const float2*)x;
    float2* o2 = (float2*)out;
    const int HD2 = DIM / 2;
    size_t xb = (size_t)b * (NH * HD2) + d2;
    float2 v0 = x2[xb], v1 = x2[xb + HD2], v2 = x2[xb + 2 * HD2], v3 = x2[xb + 3 * HD2];
    float2 xp;
    xp.x = to_tf32(hp[0] * v0.x + hp[1] * v1.x + hp[2] * v2.x + hp[3] * v3.x);
    xp.y = to_tf32(hp[0] * v0.y + hp[1] * v1.y + hp[2] * v2.y + hp[3] * v3.y);
    ((float2*)g_xpre)[(size_t)b * HD2 + d2] = xp;
#pragma unroll
    for (int n = 0; n < 4; n++) {
        float2 o;
        o.x = hr[n * 4] * v0.x + hr[n * 4 + 1] * v1.x + hr[n * 4 + 2] * v2.x + hr[n * 4 + 3] * v3.x;
        o.y = hr[n * 4] * v0.y + hr[n * 4 + 1] * v1.y + hr[n * 4 + 2] * v2.y + hr[n * 4 + 3] * v3.y;
        o2[xb + (size_t)n * HD2] = o;
    }
}

// ============================================================
// GEMM common: 128x128 block, 4 warps (2m x 2n) of 64x64, 4-stage cp.async,
// ldmatrix.x4 A-frags, conflict-free scalar-LDS B-frags (pad 136).
// Stage (floats): As[128][20] (2560) + Bs[16][136] (2176) = 4736.
// ============================================================
#define AS_PAD 20
#define BS_PAD 136
#define STG_F (128 * AS_PAD + 16 * BS_PAD)
#define STG_B (STG_F * 4)
#define NSTAGE 4
#define GEMM_SMEM (NSTAGE * STG_B)

struct GemmCtx {
    uint32_t sb;
    uint32_t a_d0, b_d0;   // cp.async dst byte offsets within stage
    uint32_t a_lm;         // ldmatrix lane-resolved byte offset within stage
    int wm, wn, tig, grp;
};

__device__ __forceinline__ void gemm_init(GemmCtx& c, const float* smbase, int tid) {
    c.sb = smem_u32(smbase);
    int lane = tid & 31, wid = tid >> 5;
    c.wm = (wid & 1) << 6;        // 0 | 64
    c.wn = (wid >> 1) << 6;       // 0 | 64
    c.tig = lane & 3;
    c.grp = lane >> 2;
    c.a_d0 = (((tid >> 2) * AS_PAD + (tid & 3) * 4) << 2);
    c.b_d0 = ((128 * AS_PAD + (tid >> 5) * BS_PAD + (tid & 31) * 4) << 2);
    c.a_lm = (((c.wm + (lane & 15)) * AS_PAD + ((lane >> 4) << 2)) << 2);
}

// A tile 128x16 (rows (tid>>2)+32j), B tile 16x128 (rows (tid>>5)+4j)
__device__ __forceinline__ void gemm_load(const GemmCtx& c, int s,
                                          const float* ap, int a_ld,
                                          const float* bp, int b_ld) {
    uint32_t so = c.sb + s * STG_B;
#pragma unroll
    for (int j = 0; j < 4; j++)
        cpa16(so + c.a_d0 + j * (32 * AS_PAD * 4), ap + (size_t)j * 32 * a_ld);
#pragma unroll
    for (int j = 0; j < 4; j++)
        cpa16(so + c.b_d0 + j * (4 * BS_PAD * 4), bp + (size_t)j * 4 * b_ld);
}

__device__ __forceinline__ void gemm_compute(const GemmCtx& c, int s,
                                             const float* smbase, float acc[4][8][4]) {
    const float* Bst = smbase + s * STG_F + 128 * AS_PAD;
    uint32_t abase = c.sb + s * STG_B + c.a_lm;
#pragma unroll
    for (int ks = 0; ks < 2; ks++) {
        const int kb = ks << 3;
        unsigned af[4][4], bf[8][2];
#pragma unroll
        for (int mt = 0; mt < 4; mt++)
            ldsm4(af[mt], abase + mt * (16 * AS_PAD * 4) + kb * 4);
        const float* br0 = Bst + (kb + c.tig) * BS_PAD + c.wn + c.grp;
#pragma unroll
        for (int nt = 0; nt < 8; nt++) {
            bf[nt][0] = __float_as_uint(br0[nt * 8]);
            bf[nt][1] = __float_as_uint(br0[4 * BS_PAD + nt * 8]);
        }
#pragma unroll
        for (int mt = 0; mt < 4; mt++)
#pragma unroll
            for (int nt = 0; nt < 8; nt++) mma8(acc[mt][nt], af[mt], bf[nt]);
    }
}

// ============================================================
// K4: G = tf32(gelu(x_pre @ W1t + b1)).  Grid: x = m-tile (B-strip reuse in L2)
// ============================================================
__global__ __launch_bounds__(128, 2) void k4_gemm1(const float* __restrict__ bias1) {
    extern __shared__ float sm[];
    const int tid = threadIdx.x;
    const int m0 = blockIdx.x << 7;
    const int n0 = blockIdx.y << 7;
    GemmCtx c;
    gemm_init(c, sm, tid);

    const float* aptr = g_xpre + (size_t)(m0 + (tid >> 2)) * DIM + (tid & 3) * 4;
    const float* bptr = g_W1t + (size_t)(tid >> 5) * DFF + n0 + (tid & 31) * 4;

    float acc[4][8][4];
#pragma unroll
    for (int i = 0; i < 4; i++)
#pragma unroll
        for (int j = 0; j < 8; j++)
#pragma unroll
            for (int q = 0; q < 4; q++) acc[i][j][q] = 0.f;

    const int T = DIM / 16;
#pragma unroll
    for (int s = 0; s < 3; s++) {
        gemm_load(c, s, aptr + s * 16, DIM, bptr + (size_t)s * 16 * DFF, DFF);
        asm volatile("cp.async.commit_group;");
    }
#pragma unroll 1
    for (int i = 0; i < T; i++) {
        asm volatile("cp.async.wait_group 2;");
        __syncthreads();
        int nx = i + 3;
        if (nx < T)
            gemm_load(c, nx & 3, aptr + nx * 16, DIM, bptr + (size_t)nx * 16 * DFF, DFF);
        asm volatile("cp.async.commit_group;");
        gemm_compute(c, i & 3, sm, acc);
    }
#pragma unroll
    for (int mt = 0; mt < 4; mt++) {
        int r = m0 + c.wm + (mt << 4) + c.grp;
#pragma unroll
        for (int nt = 0; nt < 8; nt++) {
            int cc = n0 + c.wn + (nt << 3) + (c.tig << 1);
            float bb0 = __ldg(&bias1[cc]), bb1 = __ldg(&bias1[cc + 1]);
            g_G[(size_t)r * DFF + cc]           = to_tf32(gelu_exact(acc[mt][nt][0] + bb0));
            g_G[(size_t)r * DFF + cc + 1]       = to_tf32(gelu_exact(acc[mt][nt][1] + bb1));
            g_G[(size_t)(r + 8) * DFF + cc]     = to_tf32(gelu_exact(acc[mt][nt][2] + bb0));
            g_G[(size_t)(r + 8) * DFF + cc + 1] = to_tf32(gelu_exact(acc[mt][nt][3] + bb1));
        }
    }
}

// ============================================================
// K5: H_bar = G @ W2t + b2 ; out += H_post * H_bar.  Grid: x = n-tile (W2 in L2)
// ============================================================
__global__ __launch_bounds__(128, 2) void k5_gemm2(const float* __restrict__ bias2,
                                                   float* __restrict__ out) {
    extern __shared__ float sm[];
    __shared__ float hps[128][4];
    const int tid = threadIdx.x;
    const int m0 = blockIdx.y << 7;
    const int n0 = blockIdx.x << 7;
    GemmCtx c;
    gemm_init(c, sm, tid);

    for (int i = tid; i < 512; i += 128)
        hps[i >> 2][i & 3] = g_Hpost[(size_t)(m0 + (i >> 2)) * 4 + (i & 3)];

    const float* aptr = g_G + (size_t)(m0 + (tid >> 2)) * DFF + (tid & 3) * 4;
    const float* bptr = g_W2t + (size_t)(tid >> 5) * DIM + n0 + (tid & 31) * 4;

    float acc[4][8][4];
#pragma unroll
    for (int i = 0; i < 4; i++)
#pragma unroll
        for (int j = 0; j < 8; j++)
#pragma unroll
            for (int q = 0; q < 4; q++) acc[i][j][q] = 0.f;

    const int T = DFF / 16;
#pragma unroll
    for (int s = 0; s < 3; s++) {
        gemm_load(c, s, aptr + s * 16, DFF, bptr + (size_t)s * 16 * DIM, DIM);
        asm volatile("cp.async.commit_group;");
    }
#pragma unroll 1
    for (int i = 0; i < T; i++) {
        asm volatile("cp.async.wait_group 2;");
        __syncthreads();
        int nx = i + 3;
        if (nx < T)
            gemm_load(c, nx & 3, aptr + nx * 16, DFF, bptr + (size_t)nx * 16 * DIM, DIM);
        asm volatile("cp.async.commit_group;");
        gemm_compute(c, i & 3, sm, acc);
    }
    // epilogue: out[b,h,d] += H_post[b,h] * (acc + b2[d])
#pragma unroll
    for (int mt = 0; mt < 4; mt++) {
        int rl = c.wm + (mt << 4) + c.grp;
#pragma unroll
        for (int nt = 0; nt < 8; nt++) {
            int cc = n0 + c.wn + (nt << 3) + (c.tig << 1);
            float b20 = __ldg(&bias2[cc]), b21 = __ldg(&bias2[cc + 1]);
#pragma unroll
            for (int half = 0; half < 2; half++) {
                int r = rl + half * 8;
                float h0 = acc[mt][nt][half * 2 + 0] + b20;
                float h1 = acc[mt][nt][half * 2 + 1] + b21;
                size_t base = ((size_t)(m0 + r) * 4) * DIM + cc;
#pragma unroll
                for (int h = 0; h < 4; h++) {
                    float hp = hps[r][h];
                    size_t o = base + (size_t)h * DIM;
                    out[o]     = fmaf(hp, h0, out[o]);
                    out[o + 1] = fmaf(hp, h1, out[o + 1]);
                }
            }
        }
    }
}

// ============================================================
extern "C" void kernel_launch(void* const* d_in, const int* in_sizes, int n_in,
                              void* d_out, int out_size) {
    const float* x     = (const float*)d_in[0];
    const float* w     = (const float*)d_in[1];
    const float* tpre  = (const float*)d_in[2];
    const float* tpost = (const float*)d_in[3];
    const float* tres  = (const float*)d_in[4];
    const float* apre  = (const float*)d_in[5];
    const float* apost = (const float*)d_in[6];
    const float* ares  = (const float*)d_in[7];
    const float* bpre  = (const float*)d_in[8];
    const float* bpost = (const float*)d_in[9];
    const float* bres  = (const float*)d_in[10];
    const float* b1    = (const float*)d_in[12];
    const float* b2    = (const float*)d_in[14];
    float* out = (float*)d_out;

    cudaFuncSetAttribute(k4_gemm1, cudaFuncAttributeMaxDynamicSharedMemorySize, GEMM_SMEM);
    cudaFuncSetAttribute(k5_gemm2, cudaFuncAttributeMaxDynamicSharedMemorySize, GEMM_SMEM);

    k0_cvt<<<(W1_F4 + W2_F4 + 255) / 256, 256>>>((const float*)d_in[11],
                                                 (const float*)d_in[13]);
    k1_dots<<<BATCH / 32, 256>>>(x, w, tpre, tpost, tres);
    k2_heads<<<BATCH / 256, 256>>>(apre, apost, ares, bpre, bpost, bres);
    k3_mix<<<dim3(DIM / 512, BATCH), 256>>>(x, out);
    k4_gemm1<<<dim3(BATCH / 128, DFF / 128), 128, GEMM_SMEM>>>(b1);
    k5_gemm2<<<dim3(DIM / 128, BATCH / 128), 128, GEMM_SMEM>>>(b2, out);
}